// round 13
// baseline (speedup 1.0000x reference)
#include <cuda_runtime.h>
#include <cuda_fp16.h>
#include <cstdint>

// MSAPairWeightedAverage — round 13: k5 fused into k4 via D-as-A chaining +
// atomicAdd epilogue (g_wt roundtrip eliminated); out-zero + Wout2 prep in k2'.
// S=512, I=384, C_MSA=64, C_Z=128, H=8, C=32 (H*C=256)

#define S_DIM 512
#define I_DIM 384
#define CM    64
#define CZ    128
#define H_DIM 8
#define HC    256
#define LN_EPS 1e-5f

__device__ __half g_v[(size_t)H_DIM * S_DIM * 32 * I_DIM];      // [h][n=s*32+c][j]
__device__ unsigned short g_gate16[(size_t)S_DIM * I_DIM * HC]; // [s][i][hc] u16 fixed
__device__ float  g_bias[(size_t)I_DIM * H_DIM * I_DIM];        // [i][h][j]
__device__ __half g_w[(size_t)H_DIM * I_DIM * I_DIM];           // [h][i][j]
__device__ __half g_wvt[256 * 64];                              // Wv^T swizzled f16
__device__ __half g_wgt[256 * 64];                              // Wg^T swizzled f16
__device__ __half g_wot2[8 * 64 * 64];                          // per-head Wout^T [h][d 64][c 32] sw128

#define GATE_SCALE   65535.0f
#define GATE_INV     (1.0f / 65535.0f)

// ---------------------------------------------------------------------------
__device__ __forceinline__ void cp_async16(uint32_t dst, const void* src) {
    asm volatile("cp.async.cg.shared.global [%0], [%1], 16;" :: "r"(dst), "l"(src));
}
__device__ __forceinline__ void cp_commit() { asm volatile("cp.async.commit_group;" ::: "memory"); }
__device__ __forceinline__ void cp_wait1()  { asm volatile("cp.async.wait_group 1;"  ::: "memory"); }
__device__ __forceinline__ void cp_wait0()  { asm volatile("cp.async.wait_group 0;"  ::: "memory"); }
__device__ __forceinline__ uint32_t smem_u32(const void* p) {
    uint32_t a;
    asm("{ .reg .u64 t; cvta.to.shared.u64 t, %1; cvt.u32.u64 %0, t; }" : "=r"(a) : "l"(p));
    return a;
}
__device__ __forceinline__ uint32_t swz128(uint32_t off) { return off ^ ((off >> 3) & 0x70); }
// byte offset of half element (row, k), 16B-granule XOR swizzle
__device__ __forceinline__ uint32_t bo16(int row, int k, int rowBytes) {
    return (uint32_t)(row * rowBytes + ((((k >> 3) ^ (row & 7)) << 4) | ((k & 7) << 1)));
}
__device__ __forceinline__ void mma_f16(float* d, const uint32_t* a, const uint32_t* b) {
    asm volatile(
        "mma.sync.aligned.m16n8k16.row.col.f32.f16.f16.f32 "
        "{%0,%1,%2,%3}, {%4,%5,%6,%7}, {%8,%9}, {%0,%1,%2,%3};"
        : "+f"(d[0]), "+f"(d[1]), "+f"(d[2]), "+f"(d[3])
        : "r"(a[0]), "r"(a[1]), "r"(a[2]), "r"(a[3]), "r"(b[0]), "r"(b[1]));
}
__device__ __forceinline__ uint32_t pack_gate(float a, float b) {
    uint32_t lo = __float2uint_rn(a * GATE_SCALE);
    uint32_t hi = __float2uint_rn(b * GATE_SCALE);
    return lo | (hi << 16);
}

// ---------------------------------------------------------------------------
// K2': bias GEMV blocks + 1 weight-prep block + 3072 out-zero blocks.
// ---------------------------------------------------------------------------
#define K2_BLOCKS  (I_DIM * I_DIM / 8)
#define ZERO_BLOCKS 3072                 // 3072 * 4096 floats = S*I*CM

__global__ __launch_bounds__(256) void k2_bias(
    const float* __restrict__ pair,
    const float* __restrict__ gz, const float* __restrict__ bz,
    const float* __restrict__ Wb,
    const float* __restrict__ Wv, const float* __restrict__ Wg,
    const float* __restrict__ Wo, float* __restrict__ outp)
{
    const int t = threadIdx.x;

    if (blockIdx.x > K2_BLOCKS) {        // zero d_out
        const int zi = blockIdx.x - K2_BLOCKS - 1;
        float4* o4 = (float4*)outp;
        const float4 z = make_float4(0.f, 0.f, 0.f, 0.f);
        #pragma unroll
        for (int u = 0; u < 4; u++) o4[(size_t)zi * 1024 + u * 256 + t] = z;
        return;
    }
    if (blockIdx.x == K2_BLOCKS) {       // weight prep
        #pragma unroll 4
        for (int k = 0; k < 64; k++) {
            uint32_t idx = bo16(t, k, 128) >> 1;
            g_wvt[idx] = __float2half_rn(Wv[k * 256 + t]);
            g_wgt[idx] = __float2half_rn(Wg[k * 256 + t]);
        }
        const int d = t & 63;
        for (int hh = t >> 6; hh < 8; hh += 4) {
            #pragma unroll 4
            for (int c = 0; c < 32; c++)
                g_wot2[hh * 4096 + (bo16(d, c, 128) >> 1)] =
                    __float2half_rn(Wo[(hh * 32 + c) * 64 + d]);
        }
        return;
    }

    __shared__ float Wbs[8 * 128];
    __shared__ float gzs[128], bzs[128];

    const int lane = t & 31, warp = t >> 5;
    const int row = blockIdx.x * 8 + warp;
    const int i = row / I_DIM, j = row - i * I_DIM;

    #pragma unroll
    for (int u = 0; u < 4; u++) {
        const int idx = u * 256 + t;
        const int h = idx >> 7, col = idx & 127;
        Wbs[h * 128 + col] = Wb[col * 8 + h];
    }
    if (t < 128) { gzs[t] = gz[t]; bzs[t] = bz[t]; }
    __syncthreads();

    const float* x = pair + (size_t)row * CZ;
    float xv[4];
    #pragma unroll
    for (int c = 0; c < 4; c++) xv[c] = x[lane + 32 * c];

    float s = 0.f, s2 = 0.f;
    #pragma unroll
    for (int c = 0; c < 4; c++) { s += xv[c]; s2 += xv[c] * xv[c]; }
    #pragma unroll
    for (int o = 16; o; o >>= 1) {
        s  += __shfl_xor_sync(0xffffffffu, s,  o);
        s2 += __shfl_xor_sync(0xffffffffu, s2, o);
    }
    const float mu  = s * (1.f / 128.f);
    const float var = s2 * (1.f / 128.f) - mu * mu;
    const float rs  = rsqrtf(var + LN_EPS);

    float p[8];
    #pragma unroll
    for (int h = 0; h < 8; h++) p[h] = 0.f;
    #pragma unroll
    for (int c = 0; c < 4; c++) {
        const int col = lane + 32 * c;
        const float xn = (xv[c] - mu) * rs * gzs[col] + bzs[col];
        #pragma unroll
        for (int h = 0; h < 8; h++) p[h] += xn * Wbs[h * 128 + col];
    }
    #pragma unroll
    for (int h = 0; h < 8; h++) {
        #pragma unroll
        for (int o = 16; o; o >>= 1) p[h] += __shfl_xor_sync(0xffffffffu, p[h], o);
    }
    if (lane < 8)
        g_bias[((size_t)i * H_DIM + lane) * I_DIM + j] = p[lane];
}

// ---------------------------------------------------------------------------
// K1: LN(msa) -> Ash (f16); v = A @ Wv (Dsh staged), gate = sigmoid -> u16.
// SMEM: Ash 16KB @0 ; Wsh 32KB @16384 ; Dsh [128][136] halfs @49152. 2 CTAs/SM.
// ---------------------------------------------------------------------------
__global__ __launch_bounds__(256, 2) void k1_v_gate(
    const float* __restrict__ msa,
    const float* __restrict__ ln_g, const float* __restrict__ ln_b)
{
    extern __shared__ char smc[];
    char*   Ash = smc;
    char*   Wsh = smc + 16384;
    __half* Dsh = (__half*)(smc + 49152);

    const int t    = threadIdx.x;
    const int lane = t & 31;
    const int warp = t >> 5;
    const int wm   = warp >> 1;
    const int wn   = warp & 1;
    const int r    = lane >> 2;
    const int cq   = lane & 3;

    const int rb    = blockIdx.x * 128;
    const int s_idx = rb / I_DIM;
    const int j0    = rb - s_idx * I_DIM;

    const float lg0 = ln_g[lane], lg1 = ln_g[lane + 32];
    const float lb0 = ln_b[lane], lb1 = ln_b[lane + 32];
    #pragma unroll 4
    for (int rr = 0; rr < 16; rr++) {
        const int row = warp * 16 + rr;
        const float* x = msa + (size_t)(rb + row) * CM;
        float x0 = x[lane], x1 = x[lane + 32];
        float s = x0 + x1, s2 = x0 * x0 + x1 * x1;
        #pragma unroll
        for (int o = 16; o; o >>= 1) {
            s  += __shfl_xor_sync(0xffffffffu, s,  o);
            s2 += __shfl_xor_sync(0xffffffffu, s2, o);
        }
        float mu  = s * (1.f / 64.f);
        float var = s2 * (1.f / 64.f) - mu * mu;
        float rs  = rsqrtf(var + LN_EPS);
        *(__half*)(Ash + bo16(row, lane,      128)) =
            __float2half_rn((x0 - mu) * rs * lg0 + lb0);
        *(__half*)(Ash + bo16(row, lane + 32, 128)) =
            __float2half_rn((x1 - mu) * rs * lg1 + lb1);
    }

    for (int p = 0; p < 2; p++) {
        __syncthreads();
        {
            const float4* src = (const float4*)(p ? g_wgt : g_wvt);
            float4* dst = (float4*)Wsh;
            #pragma unroll
            for (int u = 0; u < 8; u++) dst[u * 256 + t] = src[u * 256 + t];
        }
        __syncthreads();

        for (int nh = 0; nh < 2; nh++) {
            float acc[2][8][4];
            #pragma unroll
            for (int mt = 0; mt < 2; mt++)
                #pragma unroll
                for (int nt = 0; nt < 8; nt++)
                    #pragma unroll
                    for (int e = 0; e < 4; e++) acc[mt][nt][e] = 0.f;

            #pragma unroll
            for (int ks = 0; ks < 4; ks++) {
                const int klo = ks * 16 + 2 * cq, khi = klo + 8;
                uint32_t a[2][4];
                #pragma unroll
                for (int mt = 0; mt < 2; mt++) {
                    const int row0 = wm * 32 + mt * 16 + r;
                    a[mt][0] = *(const uint32_t*)(Ash + bo16(row0,     klo, 128));
                    a[mt][1] = *(const uint32_t*)(Ash + bo16(row0 + 8, klo, 128));
                    a[mt][2] = *(const uint32_t*)(Ash + bo16(row0,     khi, 128));
                    a[mt][3] = *(const uint32_t*)(Ash + bo16(row0 + 8, khi, 128));
                }
                uint32_t b[8][2];
                #pragma unroll
                for (int nt = 0; nt < 8; nt++) {
                    const int n = nh * 128 + wn * 64 + nt * 8 + r;
                    b[nt][0] = *(const uint32_t*)(Wsh + bo16(n, klo, 128));
                    b[nt][1] = *(const uint32_t*)(Wsh + bo16(n, khi, 128));
                }
                #pragma unroll
                for (int mt = 0; mt < 2; mt++)
                    #pragma unroll
                    for (int nt = 0; nt < 8; nt++)
                        mma_f16(acc[mt][nt], a[mt], b[nt]);
            }

            if (p == 0) {
                #pragma unroll
                for (int mt = 0; mt < 2; mt++) {
                    #pragma unroll
                    for (int nt = 0; nt < 8; nt++) {
                        const int ncl = wn * 64 + nt * 8 + 2 * cq;
                        const int row = wm * 32 + mt * 16 + r;
                        Dsh[ncl * 136 + row]           = __float2half_rn(acc[mt][nt][0]);
                        Dsh[(ncl + 1) * 136 + row]     = __float2half_rn(acc[mt][nt][1]);
                        Dsh[ncl * 136 + row + 8]       = __float2half_rn(acc[mt][nt][2]);
                        Dsh[(ncl + 1) * 136 + row + 8] = __float2half_rn(acc[mt][nt][3]);
                    }
                }
                __syncthreads();
                #pragma unroll
                for (int u = 0; u < 8; u++) {
                    const int idx  = u * 256 + t;
                    const int q    = idx & 15;
                    const int rloc = idx >> 4;
                    const int nc   = nh * 128 + rloc;
                    const int h    = nc >> 5, c = nc & 31;
                    float4 val = *(const float4*)(Dsh + rloc * 136 + q * 8);
                    __half* drow =
                        g_v + ((size_t)h * 16384 + s_idx * 32 + c) * I_DIM + j0;
                    ((float4*)drow)[q] = val;
                }
                __syncthreads();
            } else {
                #pragma unroll
                for (int mt = 0; mt < 2; mt++) {
                    #pragma unroll
                    for (int nt = 0; nt < 8; nt++) {
                        const int nc  = nh * 128 + wn * 64 + nt * 8 + 2 * cq;
                        const int row = wm * 32 + mt * 16 + r;
                        const size_t base = (size_t)(rb + row) * HC + nc;
                        const float s0 = 1.f / (1.f + __expf(-acc[mt][nt][0]));
                        const float s1 = 1.f / (1.f + __expf(-acc[mt][nt][1]));
                        const float s2 = 1.f / (1.f + __expf(-acc[mt][nt][2]));
                        const float s3 = 1.f / (1.f + __expf(-acc[mt][nt][3]));
                        *(uint32_t*)(g_gate16 + base)                  = pack_gate(s0, s1);
                        *(uint32_t*)(g_gate16 + base + (size_t)8 * HC) = pack_gate(s2, s3);
                    }
                }
            }
        }
    }
}

// ---------------------------------------------------------------------------
// K3: w[h][i][j] = softmax_j(bias[i][h][j])  -> f16 stores
// ---------------------------------------------------------------------------
__global__ __launch_bounds__(128) void k3_softmax()
{
    __shared__ float red[4];
    __shared__ float bval;

    const int t = threadIdx.x;
    const int lane = t & 31, warp = t >> 5;
    const int b = blockIdx.x;
    const int i = b >> 3, h = b & 7;

    const float* src = g_bias + ((size_t)i * H_DIM + h) * I_DIM;
    float x0 = src[t], x1 = src[t + 128], x2 = src[t + 256];

    float m = fmaxf(x0, fmaxf(x1, x2));
    #pragma unroll
    for (int o = 16; o; o >>= 1) m = fmaxf(m, __shfl_xor_sync(0xffffffffu, m, o));
    if (lane == 0) red[warp] = m;
    __syncthreads();
    if (t == 0) bval = fmaxf(fmaxf(red[0], red[1]), fmaxf(red[2], red[3]));
    __syncthreads();
    const float mx = bval;

    float e0 = __expf(x0 - mx), e1 = __expf(x1 - mx), e2 = __expf(x2 - mx);
    float s = e0 + e1 + e2;
    #pragma unroll
    for (int o = 16; o; o >>= 1) s += __shfl_xor_sync(0xffffffffu, s, o);
    __syncthreads();
    if (lane == 0) red[warp] = s;
    __syncthreads();
    if (t == 0) bval = red[0] + red[1] + red[2] + red[3];
    __syncthreads();
    const float inv = 1.f / bval;

    __half* dst = g_w + ((size_t)h * I_DIM + i) * I_DIM;
    dst[t]       = __float2half_rn(e0 * inv);
    dst[t + 128] = __float2half_rn(e1 * inv);
    dst[t + 256] = __float2half_rn(e2 * inv);
}

// ---------------------------------------------------------------------------
// K4: fused einsum + gate + output projection.
// Mainloop: fp16 mma GEMM per head (scalar-LDS fragments), grid (3, 128, 8),
// 2 CTAs/SM, 3-stage. Epilogue: gated D -> Dsh (buf0, f16), then GEMM2
// out[i,d] += D[i, c] * Wout2[h][d, c] per s (D-frag == A-frag), atomicAdd.
// SMEM: 3 x 32KB buffers @0 ; Wsh2 8KB @98304. Total 106496.
// ---------------------------------------------------------------------------
__global__ __launch_bounds__(256, 2) void k4_gemm(float* __restrict__ outp)
{
    extern __shared__ char smc[];
    const uint32_t sb = smem_u32(smc);

    const int t    = threadIdx.x;
    const int lane = t & 31;
    const int warp = t >> 5;
    const int wm   = warp >> 1;
    const int wn   = warp & 1;
    const int r    = lane >> 2;
    const int cq   = lane & 3;

    const int i0 = blockIdx.x * 128;
    const int n0 = blockIdx.y * 128;
    const int h  = blockIdx.z;

    const __half* Ag = g_w + ((size_t)h * I_DIM + i0) * I_DIM;
    const __half* Bg = g_v + ((size_t)h * 16384 + n0) * I_DIM;

    float acc[2][8][4];
    #pragma unroll
    for (int mt = 0; mt < 2; mt++)
        #pragma unroll
        for (int nt = 0; nt < 8; nt++)
            #pragma unroll
            for (int e = 0; e < 4; e++) acc[mt][nt][e] = 0.f;

    auto LOAD = [&](int kc, int buf) {
        const uint32_t Ab = sb + buf * 32768;
        const uint32_t Bb = Ab + 16384;
        const int k0 = kc * 64;
        #pragma unroll
        for (int u = 0; u < 4; u++) {
            int lin = u * 256 + t;
            int row = lin >> 3, q = lin & 7;
            cp_async16(Ab + swz128(row * 128 + q * 16),
                       Ag + (size_t)row * I_DIM + k0 + q * 8);
        }
        #pragma unroll
        for (int u = 0; u < 4; u++) {
            int lin = u * 256 + t;
            int row = lin >> 3, q = lin & 7;
            cp_async16(Bb + swz128(row * 128 + q * 16),
                       Bg + (size_t)row * I_DIM + k0 + q * 8);
        }
        cp_commit();
    };

    {   // Wsh2 (8KB, per-head Wout2 slice) joins commit group 0
        const uint32_t W2 = sb + 98304;
        #pragma unroll
        for (int u = 0; u < 2; u++) {
            const int idx = u * 256 + t;   // 0..511 x 16B
            cp_async16(W2 + idx * 16, g_wot2 + (size_t)h * 4096 + idx * 8);
        }
    }
    LOAD(0, 0);
    LOAD(1, 1);

    #pragma unroll 1
    for (int kc = 0; kc < 6; kc++) {
        const int buf = kc % 3;
        if (kc < 5) cp_wait1(); else cp_wait0();
        __syncthreads();
        if (kc + 2 < 6) LOAD(kc + 2, (kc + 2) % 3);

        const char* Ab = smc + buf * 32768;
        const char* Bb = Ab + 16384;

        #pragma unroll
        for (int ks = 0; ks < 4; ks++) {
            const int klo = ks * 16 + 2 * cq, khi = klo + 8;
            uint32_t a[2][4];
            #pragma unroll
            for (int mt = 0; mt < 2; mt++) {
                const int row0 = wm * 32 + mt * 16 + r;
                a[mt][0] = *(const uint32_t*)(Ab + bo16(row0,     klo, 128));
                a[mt][1] = *(const uint32_t*)(Ab + bo16(row0 + 8, klo, 128));
                a[mt][2] = *(const uint32_t*)(Ab + bo16(row0,     khi, 128));
                a[mt][3] = *(const uint32_t*)(Ab + bo16(row0 + 8, khi, 128));
            }
            uint32_t b[8][2];
            #pragma unroll
            for (int nt = 0; nt < 8; nt++) {
                const int rown = wn * 64 + nt * 8 + r;
                b[nt][0] = *(const uint32_t*)(Bb + bo16(rown, klo, 128));
                b[nt][1] = *(const uint32_t*)(Bb + bo16(rown, khi, 128));
            }
            #pragma unroll
            for (int mt = 0; mt < 2; mt++)
                #pragma unroll
                for (int nt = 0; nt < 8; nt++)
                    mma_f16(acc[mt][nt], a[mt], b[nt]);
        }
    }

    // ---- Epilogue A: gate multiply, stage as f16 into Dsh (= buf0; last read
    // of buf0 was chunk kc=3, all warps past barrier kc=4 -> safe). -------------
    __half* DshE = (__half*)smc;           // [128 rows i][128 cols n] rowBytes 256
    #pragma unroll
    for (int mt = 0; mt < 2; mt++) {
        #pragma unroll
        for (int nt = 0; nt < 8; nt++) {
            const int n_lo = wn * 64 + nt * 8 + 2 * cq;        // block-local n
            const int n_g  = n0 + n_lo;
            const int s = n_g >> 5, c = n_g & 31;
            const int row = wm * 32 + mt * 16 + r;
            const int i = i0 + row;
            const size_t base0 = ((size_t)s * I_DIM + i) * HC + h * 32 + c;
            const size_t base1 = base0 + (size_t)8 * HC;
            const uint32_t u0 = *(const uint32_t*)(g_gate16 + base0);
            const uint32_t u1 = *(const uint32_t*)(g_gate16 + base1);
            __half2 w0, w1;
            w0.x = __float2half_rn((float)(u0 & 0xffffu) * GATE_INV * acc[mt][nt][0]);
            w0.y = __float2half_rn((float)(u0 >> 16)     * GATE_INV * acc[mt][nt][1]);
            w1.x = __float2half_rn((float)(u1 & 0xffffu) * GATE_INV * acc[mt][nt][2]);
            w1.y = __float2half_rn((float)(u1 >> 16)     * GATE_INV * acc[mt][nt][3]);
            *(__half2*)((char*)DshE + bo16(row,     n_lo, 256)) = w0;
            *(__half2*)((char*)DshE + bo16(row + 8, n_lo, 256)) = w1;
        }
    }
    __syncthreads();

    // ---- Epilogue B: GEMM2 out[i, d] += D[i, s*32+c] * Wout2[h][d, c] --------
    const char* DshB = smc;
    const char* W2b  = smc + 98304;

    // hoist B frags: Wout2 slice [64 d][32 c] -> 2 k16-steps x 4 n8-tiles
    uint32_t b2[2][4][2];
    #pragma unroll
    for (int ks2 = 0; ks2 < 2; ks2++) {
        const int bklo = ks2 * 16 + 2 * cq, bkhi = bklo + 8;
        #pragma unroll
        for (int nt = 0; nt < 4; nt++) {
            const int drow = wn * 32 + nt * 8 + r;
            b2[ks2][nt][0] = *(const uint32_t*)(W2b + bo16(drow, bklo, 128));
            b2[ks2][nt][1] = *(const uint32_t*)(W2b + bo16(drow, bkhi, 128));
        }
    }

    #pragma unroll
    for (int s_loc = 0; s_loc < 4; s_loc++) {
        float acc2[2][4][4];
        #pragma unroll
        for (int mt = 0; mt < 2; mt++)
            #pragma unroll
            for (int nt = 0; nt < 4; nt++)
                #pragma unroll
                for (int e = 0; e < 4; e++) acc2[mt][nt][e] = 0.f;

        #pragma unroll
        for (int ks2 = 0; ks2 < 2; ks2++) {
            const int klo = s_loc * 32 + ks2 * 16 + 2 * cq, khi = klo + 8;
            uint32_t a[2][4];
            #pragma unroll
            for (int mt = 0; mt < 2; mt++) {
                const int row0 = wm * 32 + mt * 16 + r;
                a[mt][0] = *(const uint32_t*)(DshB + bo16(row0,     klo, 256));
                a[mt][1] = *(const uint32_t*)(DshB + bo16(row0 + 8, klo, 256));
                a[mt][2] = *(const uint32_t*)(DshB + bo16(row0,     khi, 256));
                a[mt][3] = *(const uint32_t*)(DshB + bo16(row0 + 8, khi, 256));
            }
            #pragma unroll
            for (int mt = 0; mt < 2; mt++)
                #pragma unroll
                for (int nt = 0; nt < 4; nt++)
                    mma_f16(acc2[mt][nt], a[mt], b2[ks2][nt]);
        }

        const int sg = blockIdx.y * 4 + s_loc;
        #pragma unroll
        for (int mt = 0; mt < 2; mt++) {
            #pragma unroll
            for (int nt = 0; nt < 4; nt++) {
                const int d = wn * 32 + nt * 8 + 2 * cq;
                const int i = i0 + wm * 32 + mt * 16 + r;
                float* po = outp + ((size_t)sg * I_DIM + i) * CM + d;
                atomicAdd(po,              acc2[mt][nt][0]);
                atomicAdd(po + 1,          acc2[mt][nt][1]);
                atomicAdd(po + 8 * CM,     acc2[mt][nt][2]);
                atomicAdd(po + 8 * CM + 1, acc2[mt][nt][3]);
            }
        }
    }
}

// ---------------------------------------------------------------------------
extern "C" void kernel_launch(void* const* d_in, const int* in_sizes, int n_in,
                              void* d_out, int out_size)
{
    (void)in_sizes; (void)n_in; (void)out_size;
    const float* msa  = (const float*)d_in[0];
    const float* pair = (const float*)d_in[1];
    const float* lmg  = (const float*)d_in[2];
    const float* lmb  = (const float*)d_in[3];
    const float* lpg  = (const float*)d_in[4];
    const float* lpb  = (const float*)d_in[5];
    const float* Wv   = (const float*)d_in[6];
    const float* Wb   = (const float*)d_in[7];
    const float* Wg   = (const float*)d_in[8];
    const float* Wo   = (const float*)d_in[9];
    float* outp = (float*)d_out;

    cudaFuncSetAttribute(k1_v_gate, cudaFuncAttributeMaxDynamicSharedMemorySize, 83968);
    cudaFuncSetAttribute(k4_gemm,   cudaFuncAttributeMaxDynamicSharedMemorySize, 106496);

    k2_bias<<<K2_BLOCKS + 1 + ZERO_BLOCKS, 256>>>(pair, lpg, lpb, Wb, Wv, Wg, Wo, outp);
    k1_v_gate<<<(S_DIM * I_DIM) / 128, 256, 83968>>>(msa, lmg, lmb);
    k3_softmax<<<I_DIM * H_DIM, 128>>>();
    k4_gemm<<<dim3(3, 128, 8), 256, 106496>>>(outp);
}

// round 15
// speedup vs baseline: 1.1583x; 1.1583x over previous
#include <cuda_runtime.h>
#include <cuda_fp16.h>
#include <cstdint>

// MSAPairWeightedAverage — round 14: revert r13 fusion (atomics regressed).
// Round-12 structure restored; k3 softmax folded into k1 as tail blocks.
// S=512, I=384, C_MSA=64, C_Z=128, H=8, C=32 (H*C=256)

#define S_DIM 512
#define I_DIM 384
#define CM    64
#define CZ    128
#define H_DIM 8
#define HC    256
#define LN_EPS 1e-5f

__device__ __half g_v[(size_t)H_DIM * S_DIM * 32 * I_DIM];      // [h][n=s*32+c][j]
__device__ unsigned short g_gate16[(size_t)S_DIM * I_DIM * HC]; // [s][i][hc] u16 fixed
__device__ __half g_wt[(size_t)S_DIM * I_DIM * HC];             // [s][i][hc] gate*weights
__device__ float  g_bias[(size_t)I_DIM * H_DIM * I_DIM];        // [i][h][j]
__device__ __half g_w[(size_t)H_DIM * I_DIM * I_DIM];           // [h][i][j]
__device__ __half g_wvt[256 * 64];                              // Wv^T swizzled f16
__device__ __half g_wgt[256 * 64];                              // Wg^T swizzled f16
__device__ __half g_wot[64 * 256];                              // Wout^T swizzled f16

#define GATE_SCALE   65535.0f
#define GATE_INV     (1.0f / 65535.0f)

#define K1_BLOCKS ((S_DIM * I_DIM) / 128)     // 1536
#define SM_BLOCKS ((I_DIM * H_DIM) / 2)       // 1536 (2 softmax units each)

// ---------------------------------------------------------------------------
__device__ __forceinline__ void cp_async16(uint32_t dst, const void* src) {
    asm volatile("cp.async.cg.shared.global [%0], [%1], 16;" :: "r"(dst), "l"(src));
}
__device__ __forceinline__ void cp_commit() { asm volatile("cp.async.commit_group;" ::: "memory"); }
__device__ __forceinline__ void cp_wait1()  { asm volatile("cp.async.wait_group 1;"  ::: "memory"); }
__device__ __forceinline__ void cp_wait0()  { asm volatile("cp.async.wait_group 0;"  ::: "memory"); }
__device__ __forceinline__ uint32_t smem_u32(const void* p) {
    uint32_t a;
    asm("{ .reg .u64 t; cvta.to.shared.u64 t, %1; cvt.u32.u64 %0, t; }" : "=r"(a) : "l"(p));
    return a;
}
__device__ __forceinline__ uint32_t swz128(uint32_t off) { return off ^ ((off >> 3) & 0x70); }
// byte offset of half element (row, k) with 16B-granule XOR swizzle
__device__ __forceinline__ uint32_t bo16(int row, int k, int rowBytes) {
    return (uint32_t)(row * rowBytes + ((((k >> 3) ^ (row & 7)) << 4) | ((k & 7) << 1)));
}
__device__ __forceinline__ void mma_f16(float* d, const uint32_t* a, const uint32_t* b) {
    asm volatile(
        "mma.sync.aligned.m16n8k16.row.col.f32.f16.f16.f32 "
        "{%0,%1,%2,%3}, {%4,%5,%6,%7}, {%8,%9}, {%0,%1,%2,%3};"
        : "+f"(d[0]), "+f"(d[1]), "+f"(d[2]), "+f"(d[3])
        : "r"(a[0]), "r"(a[1]), "r"(a[2]), "r"(a[3]), "r"(b[0]), "r"(b[1]));
}
__device__ __forceinline__ uint32_t pack_gate(float a, float b) {
    uint32_t lo = __float2uint_rn(a * GATE_SCALE);
    uint32_t hi = __float2uint_rn(b * GATE_SCALE);
    return lo | (hi << 16);
}

// ---------------------------------------------------------------------------
// K2': weight prep (extra block) + bias[i][h][j] = LN(pair[i][j]) @ W_bias.
// ---------------------------------------------------------------------------
#define K2_BLOCKS (I_DIM * I_DIM / 8)

__global__ __launch_bounds__(256) void k2_bias(
    const float* __restrict__ pair,
    const float* __restrict__ gz, const float* __restrict__ bz,
    const float* __restrict__ Wb,
    const float* __restrict__ Wv, const float* __restrict__ Wg,
    const float* __restrict__ Wo)
{
    const int t = threadIdx.x;

    if (blockIdx.x == K2_BLOCKS) {   // weight prep
        #pragma unroll 4
        for (int k = 0; k < 64; k++) {
            uint32_t idx = bo16(t, k, 128) >> 1;
            g_wvt[idx] = __float2half_rn(Wv[k * 256 + t]);
            g_wgt[idx] = __float2half_rn(Wg[k * 256 + t]);
        }
        const int n = t & 63, kb = (t >> 6) * 64;
        #pragma unroll 4
        for (int kk = 0; kk < 64; kk++) {
            const int k = kb + kk;
            g_wot[bo16(n, k, 512) >> 1] = __float2half_rn(Wo[k * 64 + n]);
        }
        return;
    }

    __shared__ float Wbs[8 * 128];
    __shared__ float gzs[128], bzs[128];

    const int lane = t & 31, warp = t >> 5;
    const int row = blockIdx.x * 8 + warp;
    const int i = row / I_DIM, j = row - i * I_DIM;

    #pragma unroll
    for (int u = 0; u < 4; u++) {
        const int idx = u * 256 + t;
        const int h = idx >> 7, col = idx & 127;
        Wbs[h * 128 + col] = Wb[col * 8 + h];
    }
    if (t < 128) { gzs[t] = gz[t]; bzs[t] = bz[t]; }
    __syncthreads();

    const float* x = pair + (size_t)row * CZ;
    float xv[4];
    #pragma unroll
    for (int c = 0; c < 4; c++) xv[c] = x[lane + 32 * c];

    float s = 0.f, s2 = 0.f;
    #pragma unroll
    for (int c = 0; c < 4; c++) { s += xv[c]; s2 += xv[c] * xv[c]; }
    #pragma unroll
    for (int o = 16; o; o >>= 1) {
        s  += __shfl_xor_sync(0xffffffffu, s,  o);
        s2 += __shfl_xor_sync(0xffffffffu, s2, o);
    }
    const float mu  = s * (1.f / 128.f);
    const float var = s2 * (1.f / 128.f) - mu * mu;
    const float rs  = rsqrtf(var + LN_EPS);

    float p[8];
    #pragma unroll
    for (int h = 0; h < 8; h++) p[h] = 0.f;
    #pragma unroll
    for (int c = 0; c < 4; c++) {
        const int col = lane + 32 * c;
        const float xn = (xv[c] - mu) * rs * gzs[col] + bzs[col];
        #pragma unroll
        for (int h = 0; h < 8; h++) p[h] += xn * Wbs[h * 128 + col];
    }
    #pragma unroll
    for (int h = 0; h < 8; h++) {
        #pragma unroll
        for (int o = 16; o; o >>= 1) p[h] += __shfl_xor_sync(0xffffffffu, p[h], o);
    }
    if (lane < 8)
        g_bias[((size_t)i * H_DIM + lane) * I_DIM + j] = p[lane];
}

// ---------------------------------------------------------------------------
// K13: blocks [0, K1_BLOCKS): LN(msa) -> v/gate.  Blocks [K1_BLOCKS, +SM):
// softmax over j (2 units per block, 128 thr each).  Softmax depends only on
// k2 (stream-ordered earlier); saves a kernel launch and overlaps k1's tail.
// SMEM (k1 part): Ash 16KB @0 ; Wsh 32KB @16384 ; Dsh [128][136] @49152.
// ---------------------------------------------------------------------------
__global__ __launch_bounds__(256, 2) void k13_v_gate_softmax(
    const float* __restrict__ msa,
    const float* __restrict__ ln_g, const float* __restrict__ ln_b)
{
    extern __shared__ char smc[];

    const int t    = threadIdx.x;
    const int lane = t & 31;
    const int warp = t >> 5;

    // ---------------- softmax tail blocks ----------------
    if (blockIdx.x >= K1_BLOCKS) {
        __shared__ float red2[2][4];
        __shared__ float bval2[2];
        const int sub = t >> 7;          // 0/1: two softmax units
        const int tt  = t & 127;
        const int w4  = (tt >> 5);       // 0..3 within unit
        const int b   = (blockIdx.x - K1_BLOCKS) * 2 + sub;
        const int i = b >> 3, h = b & 7;

        const float* src = g_bias + ((size_t)i * H_DIM + h) * I_DIM;
        float x0 = src[tt], x1 = src[tt + 128], x2 = src[tt + 256];

        float m = fmaxf(x0, fmaxf(x1, x2));
        #pragma unroll
        for (int o = 16; o; o >>= 1) m = fmaxf(m, __shfl_xor_sync(0xffffffffu, m, o));
        if (lane == 0) red2[sub][w4] = m;
        __syncthreads();
        if (tt == 0)
            bval2[sub] = fmaxf(fmaxf(red2[sub][0], red2[sub][1]),
                               fmaxf(red2[sub][2], red2[sub][3]));
        __syncthreads();
        const float mx = bval2[sub];

        float e0 = __expf(x0 - mx), e1 = __expf(x1 - mx), e2 = __expf(x2 - mx);
        float s = e0 + e1 + e2;
        #pragma unroll
        for (int o = 16; o; o >>= 1) s += __shfl_xor_sync(0xffffffffu, s, o);
        __syncthreads();
        if (lane == 0) red2[sub][w4] = s;
        __syncthreads();
        if (tt == 0)
            bval2[sub] = red2[sub][0] + red2[sub][1] + red2[sub][2] + red2[sub][3];
        __syncthreads();
        const float inv = 1.f / bval2[sub];

        __half* dst = g_w + ((size_t)h * I_DIM + i) * I_DIM;
        dst[tt]       = __float2half_rn(e0 * inv);
        dst[tt + 128] = __float2half_rn(e1 * inv);
        dst[tt + 256] = __float2half_rn(e2 * inv);
        return;
    }

    // ---------------- k1 blocks ----------------
    char*   Ash = smc;
    char*   Wsh = smc + 16384;
    __half* Dsh = (__half*)(smc + 49152);    // [128][136]

    const int wm = warp >> 1;
    const int wn = warp & 1;
    const int r  = lane >> 2;
    const int cq = lane & 3;

    const int rb    = blockIdx.x * 128;
    const int s_idx = rb / I_DIM;
    const int j0    = rb - s_idx * I_DIM;

    const float lg0 = ln_g[lane], lg1 = ln_g[lane + 32];
    const float lb0 = ln_b[lane], lb1 = ln_b[lane + 32];
    #pragma unroll 4
    for (int rr = 0; rr < 16; rr++) {
        const int row = warp * 16 + rr;
        const float* x = msa + (size_t)(rb + row) * CM;
        float x0 = x[lane], x1 = x[lane + 32];
        float s = x0 + x1, s2 = x0 * x0 + x1 * x1;
        #pragma unroll
        for (int o = 16; o; o >>= 1) {
            s  += __shfl_xor_sync(0xffffffffu, s,  o);
            s2 += __shfl_xor_sync(0xffffffffu, s2, o);
        }
        float mu  = s * (1.f / 64.f);
        float var = s2 * (1.f / 64.f) - mu * mu;
        float rs  = rsqrtf(var + LN_EPS);
        *(__half*)(Ash + bo16(row, lane,      128)) =
            __float2half_rn((x0 - mu) * rs * lg0 + lb0);
        *(__half*)(Ash + bo16(row, lane + 32, 128)) =
            __float2half_rn((x1 - mu) * rs * lg1 + lb1);
    }

    for (int p = 0; p < 2; p++) {
        __syncthreads();
        {
            const float4* src = (const float4*)(p ? g_wgt : g_wvt);
            float4* dst = (float4*)Wsh;
            #pragma unroll
            for (int u = 0; u < 8; u++) dst[u * 256 + t] = src[u * 256 + t];
        }
        __syncthreads();

        for (int nh = 0; nh < 2; nh++) {
            float acc[2][8][4];
            #pragma unroll
            for (int mt = 0; mt < 2; mt++)
                #pragma unroll
                for (int nt = 0; nt < 8; nt++)
                    #pragma unroll
                    for (int e = 0; e < 4; e++) acc[mt][nt][e] = 0.f;

            #pragma unroll
            for (int ks = 0; ks < 4; ks++) {              // K=64, 16 per step
                const int klo = ks * 16 + 2 * cq, khi = klo + 8;
                uint32_t a[2][4];
                #pragma unroll
                for (int mt = 0; mt < 2; mt++) {
                    const int row0 = wm * 32 + mt * 16 + r;
                    a[mt][0] = *(const uint32_t*)(Ash + bo16(row0,     klo, 128));
                    a[mt][1] = *(const uint32_t*)(Ash + bo16(row0 + 8, klo, 128));
                    a[mt][2] = *(const uint32_t*)(Ash + bo16(row0,     khi, 128));
                    a[mt][3] = *(const uint32_t*)(Ash + bo16(row0 + 8, khi, 128));
                }
                uint32_t b[8][2];
                #pragma unroll
                for (int nt = 0; nt < 8; nt++) {
                    const int n = nh * 128 + wn * 64 + nt * 8 + r;
                    b[nt][0] = *(const uint32_t*)(Wsh + bo16(n, klo, 128));
                    b[nt][1] = *(const uint32_t*)(Wsh + bo16(n, khi, 128));
                }
                #pragma unroll
                for (int mt = 0; mt < 2; mt++)
                    #pragma unroll
                    for (int nt = 0; nt < 8; nt++)
                        mma_f16(acc[mt][nt], a[mt], b[nt]);
            }

            if (p == 0) {
                #pragma unroll
                for (int mt = 0; mt < 2; mt++) {
                    #pragma unroll
                    for (int nt = 0; nt < 8; nt++) {
                        const int ncl = wn * 64 + nt * 8 + 2 * cq;
                        const int row = wm * 32 + mt * 16 + r;
                        Dsh[ncl * 136 + row]           = __float2half_rn(acc[mt][nt][0]);
                        Dsh[(ncl + 1) * 136 + row]     = __float2half_rn(acc[mt][nt][1]);
                        Dsh[ncl * 136 + row + 8]       = __float2half_rn(acc[mt][nt][2]);
                        Dsh[(ncl + 1) * 136 + row + 8] = __float2half_rn(acc[mt][nt][3]);
                    }
                }
                __syncthreads();
                #pragma unroll
                for (int u = 0; u < 8; u++) {
                    const int idx  = u * 256 + t;
                    const int q    = idx & 15;
                    const int rloc = idx >> 4;
                    const int nc   = nh * 128 + rloc;
                    const int h    = nc >> 5, c = nc & 31;
                    float4 val = *(const float4*)(Dsh + rloc * 136 + q * 8);
                    __half* drow =
                        g_v + ((size_t)h * 16384 + s_idx * 32 + c) * I_DIM + j0;
                    ((float4*)drow)[q] = val;
                }
                __syncthreads();
            } else {
                #pragma unroll
                for (int mt = 0; mt < 2; mt++) {
                    #pragma unroll
                    for (int nt = 0; nt < 8; nt++) {
                        const int nc  = nh * 128 + wn * 64 + nt * 8 + 2 * cq;
                        const int row = wm * 32 + mt * 16 + r;
                        const size_t base = (size_t)(rb + row) * HC + nc;
                        const float s0 = 1.f / (1.f + __expf(-acc[mt][nt][0]));
                        const float s1 = 1.f / (1.f + __expf(-acc[mt][nt][1]));
                        const float s2 = 1.f / (1.f + __expf(-acc[mt][nt][2]));
                        const float s3 = 1.f / (1.f + __expf(-acc[mt][nt][3]));
                        *(uint32_t*)(g_gate16 + base)                  = pack_gate(s0, s1);
                        *(uint32_t*)(g_gate16 + base + (size_t)8 * HC) = pack_gate(s2, s3);
                    }
                }
            }
        }
    }
}

// ---------------------------------------------------------------------------
// K4: fp16 mma GEMM per head (scalar-LDS fragments). Grid (3, 128, 8);
// 2 CTAs/SM; 3-stage, 1 barrier. K=384 in 6 chunks of 64 halfs. SMEM 3x32KB.
// ---------------------------------------------------------------------------
__global__ __launch_bounds__(256, 2) void k4_gemm()
{
    extern __shared__ char smc[];
    const uint32_t sb = smem_u32(smc);

    const int t    = threadIdx.x;
    const int lane = t & 31;
    const int warp = t >> 5;
    const int wm   = warp >> 1;
    const int wn   = warp & 1;
    const int r    = lane >> 2;
    const int cq   = lane & 3;

    const int i0 = blockIdx.x * 128;
    const int n0 = blockIdx.y * 128;
    const int h  = blockIdx.z;

    const __half* Ag = g_w + ((size_t)h * I_DIM + i0) * I_DIM;
    const __half* Bg = g_v + ((size_t)h * 16384 + n0) * I_DIM;

    float acc[2][8][4];
    #pragma unroll
    for (int mt = 0; mt < 2; mt++)
        #pragma unroll
        for (int nt = 0; nt < 8; nt++)
            #pragma unroll
            for (int e = 0; e < 4; e++) acc[mt][nt][e] = 0.f;

    auto LOAD = [&](int kc, int buf) {
        const uint32_t Ab = sb + buf * 32768;
        const uint32_t Bb = Ab + 16384;
        const int k0 = kc * 64;
        #pragma unroll
        for (int u = 0; u < 4; u++) {
            int lin = u * 256 + t;
            int row = lin >> 3, q = lin & 7;
            cp_async16(Ab + swz128(row * 128 + q * 16),
                       Ag + (size_t)row * I_DIM + k0 + q * 8);
        }
        #pragma unroll
        for (int u = 0; u < 4; u++) {
            int lin = u * 256 + t;
            int row = lin >> 3, q = lin & 7;
            cp_async16(Bb + swz128(row * 128 + q * 16),
                       Bg + (size_t)row * I_DIM + k0 + q * 8);
        }
        cp_commit();
    };

    LOAD(0, 0);
    LOAD(1, 1);

    #pragma unroll 1
    for (int kc = 0; kc < 6; kc++) {
        const int buf = kc % 3;
        if (kc < 5) cp_wait1(); else cp_wait0();
        __syncthreads();
        if (kc + 2 < 6) LOAD(kc + 2, (kc + 2) % 3);

        const char* Ab = smc + buf * 32768;
        const char* Bb = Ab + 16384;

        #pragma unroll
        for (int ks = 0; ks < 4; ks++) {
            const int klo = ks * 16 + 2 * cq, khi = klo + 8;
            uint32_t a[2][4];
            #pragma unroll
            for (int mt = 0; mt < 2; mt++) {
                const int row0 = wm * 32 + mt * 16 + r;
                a[mt][0] = *(const uint32_t*)(Ab + bo16(row0,     klo, 128));
                a[mt][1] = *(const uint32_t*)(Ab + bo16(row0 + 8, klo, 128));
                a[mt][2] = *(const uint32_t*)(Ab + bo16(row0,     khi, 128));
                a[mt][3] = *(const uint32_t*)(Ab + bo16(row0 + 8, khi, 128));
            }
            uint32_t b[8][2];
            #pragma unroll
            for (int nt = 0; nt < 8; nt++) {
                const int rown = wn * 64 + nt * 8 + r;
                b[nt][0] = *(const uint32_t*)(Bb + bo16(rown, klo, 128));
                b[nt][1] = *(const uint32_t*)(Bb + bo16(rown, khi, 128));
            }
            #pragma unroll
            for (int mt = 0; mt < 2; mt++)
                #pragma unroll
                for (int nt = 0; nt < 8; nt++)
                    mma_f16(acc[mt][nt], a[mt], b[nt]);
        }
    }

    #pragma unroll
    for (int mt = 0; mt < 2; mt++) {
        #pragma unroll
        for (int nt = 0; nt < 8; nt++) {
            const int n_lo = n0 + wn * 64 + nt * 8 + 2 * cq;
            const int s = n_lo >> 5, c = n_lo & 31;
            const int i = i0 + wm * 32 + mt * 16 + r;
            const size_t base0 = ((size_t)s * I_DIM + i) * HC + h * 32 + c;
            const size_t base1 = base0 + (size_t)8 * HC;
            const uint32_t u0 = *(const uint32_t*)(g_gate16 + base0);
            const uint32_t u1 = *(const uint32_t*)(g_gate16 + base1);
            __half2 w0, w1;
            w0.x = __float2half_rn((float)(u0 & 0xffffu) * GATE_INV * acc[mt][nt][0]);
            w0.y = __float2half_rn((float)(u0 >> 16)     * GATE_INV * acc[mt][nt][1]);
            w1.x = __float2half_rn((float)(u1 & 0xffffu) * GATE_INV * acc[mt][nt][2]);
            w1.y = __float2half_rn((float)(u1 >> 16)     * GATE_INV * acc[mt][nt][3]);
            *(__half2*)(g_wt + base0) = w0;
            *(__half2*)(g_wt + base1) = w1;
        }
    }
}

// ---------------------------------------------------------------------------
// K5: out = g_wt @ W_out via fp16 mma (scalar-LDS fragments). 2 CTAs/SM;
// 3-stage, 1 barrier. SMEM: Wsh 32KB @0 ; 3 x 16KB @32768. Total 80KB.
// ---------------------------------------------------------------------------
__global__ __launch_bounds__(256, 2) void k5_out(float* __restrict__ outp)
{
    extern __shared__ char smc[];
    const uint32_t sb = smem_u32(smc);
    char* Wsh = smc;

    const int t    = threadIdx.x;
    const int lane = t & 31;
    const int warp = t >> 5;
    const int wm   = warp >> 1;
    const int wn   = warp & 1;
    const int r    = lane >> 2;
    const int cq   = lane & 3;
    const int rb   = blockIdx.x * 128;

    {
        const float4* src = (const float4*)g_wot;
        float4* dst = (float4*)Wsh;
        #pragma unroll
        for (int u = 0; u < 8; u++) dst[u * 256 + t] = src[u * 256 + t];
    }

    const __half* Agl = g_wt + (size_t)rb * HC;

    auto LOAD = [&](int kc, int buf) {
        const uint32_t Ab = sb + 32768 + buf * 16384;
        const int k0 = kc * 64;
        #pragma unroll
        for (int u = 0; u < 4; u++) {
            int lin = u * 256 + t;
            int row = lin >> 3, q = lin & 7;
            cp_async16(Ab + swz128(row * 128 + q * 16),
                       Agl + (size_t)row * HC + k0 + q * 8);
        }
        cp_commit();
    };

    float acc[2][4][4];
    #pragma unroll
    for (int mt = 0; mt < 2; mt++)
        #pragma unroll
        for (int nt = 0; nt < 4; nt++)
            #pragma unroll
            for (int e = 0; e < 4; e++) acc[mt][nt][e] = 0.f;

    LOAD(0, 0);
    LOAD(1, 1);

    #pragma unroll 1
    for (int kc = 0; kc < 4; kc++) {
        const int buf = kc % 3;
        if (kc < 3) cp_wait1(); else cp_wait0();
        __syncthreads();
        if (kc + 2 < 4) LOAD(kc + 2, (kc + 2) % 3);

        const char* Ab = smc + 32768 + buf * 16384;

        #pragma unroll
        for (int ks = 0; ks < 4; ks++) {
            const int klo = ks * 16 + 2 * cq, khi = klo + 8;
            const int gklo = kc * 64 + klo, gkhi = kc * 64 + khi;
            uint32_t a[2][4];
            #pragma unroll
            for (int mt = 0; mt < 2; mt++) {
                const int row0 = wm * 32 + mt * 16 + r;
                a[mt][0] = *(const uint32_t*)(Ab + bo16(row0,     klo, 128));
                a[mt][1] = *(const uint32_t*)(Ab + bo16(row0 + 8, klo, 128));
                a[mt][2] = *(const uint32_t*)(Ab + bo16(row0,     khi, 128));
                a[mt][3] = *(const uint32_t*)(Ab + bo16(row0 + 8, khi, 128));
            }
            uint32_t b[4][2];
            #pragma unroll
            for (int nt = 0; nt < 4; nt++) {
                const int n = wn * 32 + nt * 8 + r;
                b[nt][0] = *(const uint32_t*)(Wsh + bo16(n, gklo, 512));
                b[nt][1] = *(const uint32_t*)(Wsh + bo16(n, gkhi, 512));
            }
            #pragma unroll
            for (int mt = 0; mt < 2; mt++)
                #pragma unroll
                for (int nt = 0; nt < 4; nt++)
                    mma_f16(acc[mt][nt], a[mt], b[nt]);
        }
    }

    #pragma unroll
    for (int mt = 0; mt < 2; mt++) {
        #pragma unroll
        for (int nt = 0; nt < 4; nt++) {
            const int n   = wn * 32 + nt * 8 + 2 * cq;
            const int row = rb + wm * 32 + mt * 16 + r;
            *(float2*)(outp + (size_t)row * CM + n) =
                make_float2(acc[mt][nt][0], acc[mt][nt][1]);
            *(float2*)(outp + (size_t)(row + 8) * CM + n) =
                make_float2(acc[mt][nt][2], acc[mt][nt][3]);
        }
    }
}

// ---------------------------------------------------------------------------
extern "C" void kernel_launch(void* const* d_in, const int* in_sizes, int n_in,
                              void* d_out, int out_size)
{
    (void)in_sizes; (void)n_in; (void)out_size;
    const float* msa  = (const float*)d_in[0];
    const float* pair = (const float*)d_in[1];
    const float* lmg  = (const float*)d_in[2];
    const float* lmb  = (const float*)d_in[3];
    const float* lpg  = (const float*)d_in[4];
    const float* lpb  = (const float*)d_in[5];
    const float* Wv   = (const float*)d_in[6];
    const float* Wb   = (const float*)d_in[7];
    const float* Wg   = (const float*)d_in[8];
    const float* Wo   = (const float*)d_in[9];
    float* outp = (float*)d_out;

    cudaFuncSetAttribute(k13_v_gate_softmax,
                         cudaFuncAttributeMaxDynamicSharedMemorySize, 83968);
    cudaFuncSetAttribute(k4_gemm, cudaFuncAttributeMaxDynamicSharedMemorySize, 98304);
    cudaFuncSetAttribute(k5_out,  cudaFuncAttributeMaxDynamicSharedMemorySize, 81920);

    k2_bias<<<K2_BLOCKS + 1, 256>>>(pair, lpg, lpb, Wb, Wv, Wg, Wo);
    k13_v_gate_softmax<<<K1_BLOCKS + SM_BLOCKS, 256, 83968>>>(msa, lmg, lmb);
    k4_gemm<<<dim3(3, 128, 8), 256, 98304>>>();
    k5_out<<<(S_DIM * I_DIM) / 128, 256, 81920>>>(outp);
}